// round 4
// baseline (speedup 1.0000x reference)
#include <cuda_runtime.h>
#include <cstdint>

// ---------------------------------------------------------------------------
// GraphSAGE (3x SAGEConv mean + linear head), N=50000, E=600000, 16->128->128->128->4
//
// Strategy:
//   - Build CSR (by dst) each launch: count -> single-block scan -> fill.
//   - Layer 1: aggregate x (16-dim) then fused small transform.
//   - Layers 2/3: aggregate h (128-dim, warp/node float4 gather from L2),
//     then K=256 GEMM [agg|h] @ [Wl|Wr]^T using packed fp32x2 FMA (fma.rn.f32x2).
//   - Head: warp/node dot with Wh.
// All scratch in __device__ globals (no allocations). All launches on the
// default stream -> graph-capturable.
// ---------------------------------------------------------------------------

#define NN 50000
#define NE 600000

__device__ int   g_is64;
__device__ int   g_deg[NN];
__device__ int   g_off[NN + 1];
__device__ int   g_cur[NN];
__device__ int   g_srcl[NE];
__device__ float g_agg16[NN * 16];
__device__ float g_agg[NN * 128];
__device__ float g_h1[NN * 128];
__device__ float g_h2[NN * 128];
__device__ float g_U[2 * 256 * 128];   // k-major transposed [Wl|Wr] for layers 2,3

// ---------------- fp32x2 helpers ----------------
__device__ __forceinline__ unsigned long long pack2f(float a, float b) {
    unsigned long long r;
    asm("mov.b64 %0, {%1, %2};" : "=l"(r) : "f"(a), "f"(b));
    return r;
}
__device__ __forceinline__ void unpack2f(unsigned long long v, float& a, float& b) {
    asm("mov.b64 {%0, %1}, %2;" : "=f"(a), "=f"(b) : "l"(v));
}
__device__ __forceinline__ unsigned long long ffma2(unsigned long long a,
                                                    unsigned long long b,
                                                    unsigned long long c) {
    unsigned long long d;
    asm("fma.rn.f32x2 %0, %1, %2, %3;" : "=l"(d) : "l"(a), "l"(b), "l"(c));
    return d;
}

// ---------------- edge-index dtype detect ----------------
// int64 little-endian with values < 2^31 => every odd int32 word is 0.
__global__ void detect_k(const void* ei) {
    if (threadIdx.x == 0 && blockIdx.x == 0) {
        const int* p = (const int*)ei;
        int acc = 0;
        for (int i = 1; i < 256; i += 2) acc |= p[i];
        g_is64 = (acc == 0) ? 1 : 0;
    }
}

__device__ __forceinline__ int edge_val(const void* ei, long long idx, int is64) {
    if (is64) return (int)((const long long*)ei)[idx];
    return ((const int*)ei)[idx];
}

// ---------------- CSR build ----------------
__global__ void zero_deg_k(int n) {
    int i = blockIdx.x * blockDim.x + threadIdx.x;
    if (i < n) g_deg[i] = 0;
}

__global__ void count_k(const void* ei, int e) {
    int i = blockIdx.x * blockDim.x + threadIdx.x;
    if (i >= e) return;
    int is64 = g_is64;
    int d = edge_val(ei, (long long)e + i, is64);
    atomicAdd(&g_deg[d], 1);
}

__global__ void scan_k(int n) {
    __shared__ int wsum[32];
    __shared__ int carry_s;
    int tid = threadIdx.x, lane = tid & 31, wid = tid >> 5;
    if (tid == 0) carry_s = 0;
    __syncthreads();
    for (int base = 0; base < n; base += 1024) {
        int i = base + tid;
        int v = (i < n) ? g_deg[i] : 0;
        int xv = v;
#pragma unroll
        for (int o = 1; o < 32; o <<= 1) {
            int y = __shfl_up_sync(0xffffffffu, xv, o);
            if (lane >= o) xv += y;
        }
        if (lane == 31) wsum[wid] = xv;
        __syncthreads();
        if (wid == 0) {
            int wv = wsum[lane];
            int xw = wv;
#pragma unroll
            for (int o = 1; o < 32; o <<= 1) {
                int y = __shfl_up_sync(0xffffffffu, xw, o);
                if (lane >= o) xw += y;
            }
            wsum[lane] = xw - wv;   // exclusive warp offsets
        }
        __syncthreads();
        int incl = xv + wsum[wid];
        int c = carry_s;
        if (i < n) g_off[i] = c + incl - v;  // exclusive scan
        __syncthreads();
        if (tid == 1023) carry_s = c + incl;
        __syncthreads();
    }
    if (threadIdx.x == 0) g_off[n] = carry_s;
}

__global__ void cpcur_k(int n) {
    int i = blockIdx.x * blockDim.x + threadIdx.x;
    if (i < n) g_cur[i] = g_off[i];
}

__global__ void fill_k(const void* ei, int e) {
    int i = blockIdx.x * blockDim.x + threadIdx.x;
    if (i >= e) return;
    int is64 = g_is64;
    int s = edge_val(ei, i, is64);
    int d = edge_val(ei, (long long)e + i, is64);
    int p = atomicAdd(&g_cur[d], 1);
    g_srcl[p] = s;
}

// ---------------- weight prep: U[k][o] = k<128 ? Wl[o][k] : Wr[o][k-128] ----------------
__global__ void prepU_k(const float* __restrict__ Wl2, const float* __restrict__ Wr2,
                        const float* __restrict__ Wl3, const float* __restrict__ Wr3) {
    int idx = blockIdx.x * blockDim.x + threadIdx.x;   // 0 .. 65535
    int layer = idx >> 15;
    int r = idx & 32767;
    int k = r >> 7;
    int o = r & 127;
    const float* Wl = layer ? Wl3 : Wl2;
    const float* Wr = layer ? Wr3 : Wr2;
    float v = (k < 128) ? Wl[o * 128 + k] : Wr[o * 128 + (k - 128)];
    g_U[layer * 32768 + k * 128 + o] = v;
}

// ---------------- layer-1 aggregation (16-dim mean of x over in-neighbors) ----------------
__global__ __launch_bounds__(256) void agg16_k(const float* __restrict__ x, int n) {
    int w = (blockIdx.x * blockDim.x + threadIdx.x) >> 5;
    if (w >= n) return;
    int lane = threadIdx.x & 31;
    int e0 = g_off[w], e1 = g_off[w + 1];
    float s = 0.f;
    for (int e = e0; e < e1; e++) {
        int si = g_srcl[e];
        if (lane < 16) s += x[si * 16 + lane];
    }
    float inv = 1.0f / (float)max(e1 - e0, 1);
    if (lane < 16) g_agg16[w * 16 + lane] = s * inv;
}

// ---------------- layer-1 transform: h1 = relu(agg16@Wl1^T + x@Wr1^T + b1) ----------------
__global__ __launch_bounds__(128) void l1_k(const float* __restrict__ x,
                                            const float* __restrict__ Wl1,
                                            const float* __restrict__ Wr1,
                                            const float* __restrict__ b1, int n) {
    __shared__ float sA[32 * 16];
    __shared__ float sX[32 * 16];
    int o = threadIdx.x;           // 0..127 output channel
    int nb = blockIdx.x * 32;
    float wl[16], wr[16];
#pragma unroll
    for (int k = 0; k < 16; k++) { wl[k] = Wl1[o * 16 + k]; wr[k] = Wr1[o * 16 + k]; }
    float bb = b1[o];
    int cnt = min(32, n - nb);
    for (int i = o; i < cnt * 16; i += 128) {
        sA[i] = g_agg16[nb * 16 + i];
        sX[i] = x[nb * 16 + i];
    }
    __syncthreads();
    for (int nn = 0; nn < cnt; nn++) {
        float acc = bb;
#pragma unroll
        for (int k = 0; k < 16; k++)
            acc += sA[nn * 16 + k] * wl[k] + sX[nn * 16 + k] * wr[k];
        g_h1[(nb + nn) * 128 + o] = fmaxf(acc, 0.f);
    }
}

// ---------------- 128-dim aggregation: g_agg[n] = mean over in-neighbors of h[src] ----------------
__global__ __launch_bounds__(256) void agg128_k(int which, int n) {
    const float* __restrict__ h = (which == 1) ? g_h1 : g_h2;
    int w = (blockIdx.x * blockDim.x + threadIdx.x) >> 5;
    if (w >= n) return;
    int lane = threadIdx.x & 31;
    int f = lane * 4;
    int e0 = g_off[w], e1 = g_off[w + 1];
    float4 s = make_float4(0.f, 0.f, 0.f, 0.f);
    int e = e0;
    for (; e + 1 < e1; e += 2) {
        int s0 = g_srcl[e];
        int s1 = g_srcl[e + 1];
        float4 v0 = *(const float4*)(h + (size_t)s0 * 128 + f);
        float4 v1 = *(const float4*)(h + (size_t)s1 * 128 + f);
        s.x += v0.x + v1.x; s.y += v0.y + v1.y;
        s.z += v0.z + v1.z; s.w += v0.w + v1.w;
    }
    if (e < e1) {
        int s0 = g_srcl[e];
        float4 v0 = *(const float4*)(h + (size_t)s0 * 128 + f);
        s.x += v0.x; s.y += v0.y; s.z += v0.z; s.w += v0.w;
    }
    float inv = 1.0f / (float)max(e1 - e0, 1);
    s.x *= inv; s.y *= inv; s.z *= inv; s.w *= inv;
    *(float4*)(g_agg + (size_t)w * 128 + f) = s;
}

// ---------------- GEMM: hout = relu([agg|hprev] @ U + b), fp32x2 ----------------
// Block: 128 nodes x 128 outputs, 256 threads, thread = 8 nodes x 8 outputs.
__global__ __launch_bounds__(256, 2) void gemm_k(int layer, const float* __restrict__ bias, int n) {
    __shared__ float As[128 * 36];     // [node][k] pad 36 (16B-aligned float4 stores)
    __shared__ float Bs[32 * 128];     // [k][o]
    const float* __restrict__ hprev = (layer == 2) ? g_h1 : g_h2;
    float* __restrict__ hout        = (layer == 2) ? g_h2 : g_h1;
    const float* __restrict__ U     = g_U + (layer - 2) * (256 * 128);

    int tid = threadIdx.x;
    int tx = tid & 15;        // output group: o0 = tx*8
    int ty = tid >> 4;        // node group:  n0 = ty*8
    int nb = blockIdx.x * 128;
    int o0 = tx * 8;

    unsigned long long acc[8][4];
#pragma unroll
    for (int i = 0; i < 8; i++)
#pragma unroll
        for (int j = 0; j < 4; j++) acc[i][j] = 0ull;

    for (int kb = 0; kb < 256; kb += 32) {
        const float* src = (kb < 128) ? (g_agg + kb) : (hprev + (kb - 128));
        // stage A: 128 nodes x 32 k
#pragma unroll
        for (int r = 0; r < 4; r++) {
            int lf = tid + r * 256;        // 0..1023 float4s
            int nnn = lf >> 3;
            int kq = lf & 7;
            int gn = nb + nnn;
            float4 v;
            if (gn < n) v = *(const float4*)(src + (size_t)gn * 128 + kq * 4);
            else        v = make_float4(0.f, 0.f, 0.f, 0.f);
            *(float4*)&As[nnn * 36 + kq * 4] = v;
        }
        // stage B: 32 k x 128 o
#pragma unroll
        for (int r = 0; r < 4; r++) {
            int lf = tid + r * 256;
            int k = lf >> 5;
            int oq = lf & 31;
            *(float4*)&Bs[k * 128 + oq * 4] = *(const float4*)(U + (size_t)(kb + k) * 128 + oq * 4);
        }
        __syncthreads();
#pragma unroll 4
        for (int k = 0; k < 32; k++) {
            ulonglong2 w0 = *(const ulonglong2*)&Bs[k * 128 + o0];       // outputs o0..o0+3
            ulonglong2 w1 = *(const ulonglong2*)&Bs[k * 128 + o0 + 4];   // outputs o0+4..o0+7
#pragma unroll
            for (int i2 = 0; i2 < 8; i2++) {
                float a = As[(ty * 8 + i2) * 36 + k];
                unsigned long long aa = pack2f(a, a);
                acc[i2][0] = ffma2(aa, w0.x, acc[i2][0]);
                acc[i2][1] = ffma2(aa, w0.y, acc[i2][1]);
                acc[i2][2] = ffma2(aa, w1.x, acc[i2][2]);
                acc[i2][3] = ffma2(aa, w1.y, acc[i2][3]);
            }
        }
        __syncthreads();
    }

    float bv[8];
    *(float4*)&bv[0] = *(const float4*)(bias + o0);
    *(float4*)&bv[4] = *(const float4*)(bias + o0 + 4);
#pragma unroll
    for (int i2 = 0; i2 < 8; i2++) {
        int gn = nb + ty * 8 + i2;
        if (gn < n) {
            float r[8];
#pragma unroll
            for (int j = 0; j < 4; j++) unpack2f(acc[i2][j], r[2 * j], r[2 * j + 1]);
#pragma unroll
            for (int j = 0; j < 8; j++) r[j] = fmaxf(r[j] + bv[j], 0.f);
            float* dst = hout + (size_t)gn * 128 + o0;
            *(float4*)dst = make_float4(r[0], r[1], r[2], r[3]);
            *(float4*)(dst + 4) = make_float4(r[4], r[5], r[6], r[7]);
        }
    }
}

// ---------------- head: out = h3 @ Wh^T + bh ----------------
__global__ __launch_bounds__(128) void head_k(const float* __restrict__ Wh,
                                              const float* __restrict__ bh,
                                              float* __restrict__ out, int n) {
    int w = (blockIdx.x * blockDim.x + threadIdx.x) >> 5;
    if (w >= n) return;
    int lane = threadIdx.x & 31;
    float4 hv = *(const float4*)(g_h1 + (size_t)w * 128 + lane * 4);   // layer3 output lives in g_h1
#pragma unroll
    for (int o = 0; o < 4; o++) {
        float4 wv = *(const float4*)(Wh + o * 128 + lane * 4);
        float p = hv.x * wv.x + hv.y * wv.y + hv.z * wv.z + hv.w * wv.w;
#pragma unroll
        for (int ofs = 16; ofs; ofs >>= 1) p += __shfl_down_sync(0xffffffffu, p, ofs);
        if (lane == 0) out[w * 4 + o] = p + bh[o];
    }
}

// ---------------- host ----------------
extern "C" void kernel_launch(void* const* d_in, const int* in_sizes, int n_in,
                              void* d_out, int out_size) {
    const float* x   = (const float*)d_in[0];
    const void*  ei  = d_in[1];
    const float* Wl1 = (const float*)d_in[2];
    const float* Wr1 = (const float*)d_in[3];
    const float* b1  = (const float*)d_in[4];
    const float* Wl2 = (const float*)d_in[5];
    const float* Wr2 = (const float*)d_in[6];
    const float* b2  = (const float*)d_in[7];
    const float* Wl3 = (const float*)d_in[8];
    const float* Wr3 = (const float*)d_in[9];
    const float* b3  = (const float*)d_in[10];
    const float* Wh  = (const float*)d_in[11];
    const float* bh  = (const float*)d_in[12];
    float* out = (float*)d_out;

    int n = in_sizes[0] / 16;      // 50000
    int e = in_sizes[1] / 2;       // 600000
    if (n > NN) n = NN;
    if (e > NE) e = NE;

    int gb_e = (e + 255) / 256;
    int gb_n = (n + 255) / 256;

    // CSR build
    detect_k<<<1, 32>>>(ei);
    zero_deg_k<<<gb_n, 256>>>(n);
    count_k<<<gb_e, 256>>>(ei, e);
    scan_k<<<1, 1024>>>(n);
    cpcur_k<<<gb_n, 256>>>(n);
    fill_k<<<gb_e, 256>>>(ei, e);

    // weight prep for layers 2,3
    prepU_k<<<256, 256>>>(Wl2, Wr2, Wl3, Wr3);

    // layer 1
    agg16_k<<<(n + 7) / 8, 256>>>(x, n);
    l1_k<<<(n + 31) / 32, 128>>>(x, Wl1, Wr1, b1, n);

    // layer 2
    agg128_k<<<(n + 7) / 8, 256>>>(1, n);
    gemm_k<<<(n + 127) / 128, 256>>>(2, b2, n);

    // layer 3
    agg128_k<<<(n + 7) / 8, 256>>>(2, n);
    gemm_k<<<(n + 127) / 128, 256>>>(3, b3, n);

    // head
    head_k<<<(n + 3) / 4, 128>>>(Wh, bh, out, n);
}